// round 8
// baseline (speedup 1.0000x reference)
#include <cuda_runtime.h>
#include <cuda_bf16.h>
#include <cuda_fp16.h>
#include <math.h>
#include <cstdint>

#define Bb      2
#define Ll      2048
#define HIDDEN_ 2048
#define PROJ_   8512
#define INTER_  4096
#define CONVD_  4352
#define NH_     64
#define HD_     64
#define ST_     128
#define NC_     8
#define CS_     256
#define MT      (Bb*Ll)      // 4096
#define NP1     8576

#define RES_SCALE 2048.f
#define RES_INV   (1.f/2048.f)

// ---------------- static scratch ----------------
__device__ float g_proj  [(size_t)MT*PROJ_];
__device__ float g_xbc   [(size_t)MT*CONVD_];
__device__ float g_y     [(size_t)MT*INTER_];
__device__ float g_states[(size_t)Bb*NC_*NH_*HD_*ST_];
__device__ float g_prev  [(size_t)Bb*NC_*NH_*HD_*ST_];
__device__ float g_cum   [(size_t)Bb*NH_*Ll];
__device__ float g_alast [(size_t)Bb*NH_*NC_];
__device__ float g_P     [(size_t)Bb*NC_*CS_*CS_];
__device__ __half g_Af [(size_t)MT*INTER_];
__device__ __half g_W1h[(size_t)NP1*HIDDEN_];
__device__ __half g_W1l[(size_t)NP1*HIDDEN_];
__device__ __half g_W2h[(size_t)HIDDEN_*INTER_];
__device__ __half g_W2l[(size_t)HIDDEN_*INTER_];

// ======================= warp-MMA helpers ====================
__device__ __forceinline__ uint32_t cvta_smem(const void* p) {
    uint32_t a;
    asm("{ .reg .u64 t; cvta.to.shared.u64 t, %1; cvt.u32.u64 %0, t; }"
        : "=r"(a) : "l"(p));
    return a;
}

__device__ __forceinline__ void ldsm4(uint32_t* r, uint32_t addr) {
    asm volatile("ldmatrix.sync.aligned.m8n8.x4.shared.b16 {%0,%1,%2,%3}, [%4];"
                 : "=r"(r[0]), "=r"(r[1]), "=r"(r[2]), "=r"(r[3]) : "r"(addr));
}

__device__ __forceinline__ void mma16816(float* c, const uint32_t* a,
                                         uint32_t b0, uint32_t b1) {
    asm volatile(
        "mma.sync.aligned.m16n8k16.row.col.f32.f16.f16.f32 "
        "{%0,%1,%2,%3}, {%4,%5,%6,%7}, {%8,%9}, {%0,%1,%2,%3};"
        : "+f"(c[0]), "+f"(c[1]), "+f"(c[2]), "+f"(c[3])
        : "r"(a[0]), "r"(a[1]), "r"(a[2]), "r"(a[3]), "r"(b0), "r"(b1));
}

__device__ __forceinline__ void mma16816h(uint32_t* c, const uint32_t* a,
                                          uint32_t b0, uint32_t b1) {
    asm volatile(
        "mma.sync.aligned.m16n8k16.row.col.f16.f16.f16.f16 "
        "{%0,%1}, {%2,%3,%4,%5}, {%6,%7}, {%0,%1};"
        : "+r"(c[0]), "+r"(c[1])
        : "r"(a[0]), "r"(a[1]), "r"(a[2]), "r"(a[3]), "r"(b0), "r"(b1));
}

#define CPASYNC16(sa, ga) \
    asm volatile("cp.async.cg.shared.global [%0], [%1], 16;" :: "r"(sa), "l"(ga) : "memory")

// GEMM tiling: BM=128, BN=64, BK=64, 128 threads (4 warps of 64x32), 3 stages
#define ATILEB 16384u
#define WTILEB 8192u
#define STAGEB 32768u
#define NSTG   3
#define GSMEM  (1024 + NSTG*32768)   // 99328

// =========================================================================
// 2-pass fp16 tensor-core GEMM: C = A*(Wh + Wl/2048)^T + bias
// 4 warps, 2x2 warp grid, warp tile 64(M) x 32(N): mma:ldsm ratio 4.0
// =========================================================================
__global__ __launch_bounds__(128, 2)
void tc_gemm_bias(
    const __half* __restrict__ A,
    const __half* __restrict__ Wh, const __half* __restrict__ Wl,
    const float* __restrict__ bias, float* __restrict__ C, int N, int K)
{
    extern __shared__ __align__(128) char smem[];
    const int tid = threadIdx.x;
    const int lid = tid & 31, wid = tid >> 5;
    uint32_t sb = cvta_smem(smem);
    uint32_t tb = (sb + 1023u) & ~1023u;

    const size_t arow = (size_t)blockIdx.y * 128;
    const size_t brow = (size_t)blockIdx.x * 64;
    const int NCH = K >> 6;

    // ---- loader: 128 threads, 16 cp.async/thread/stage ----
    const int seg = tid & 7, r0 = tid >> 3;       // r0: 0..15
    uint32_t soA[8];
#pragma unroll
    for (int k = 0; k < 8; k++) {
        uint32_t off = (uint32_t)((r0 + 16 * k) * 128 + seg * 16);
        soA[k] = off ^ ((off >> 3) & 0x70);
    }
    const __half* pA  = A  + (arow + r0) * (size_t)K + (seg << 3);
    const __half* pWh = Wh + (brow + r0) * (size_t)K + (seg << 3);
    const __half* pWl = Wl + (brow + r0) * (size_t)K + (seg << 3);
    const size_t off16 = (size_t)16 * K;

#define LOAD_STAGE(s)                                                     \
    do {                                                                  \
        uint32_t stb_ = tb + (uint32_t)(s) * STAGEB;                      \
        CPASYNC16(stb_ + soA[0], pA);                                     \
        CPASYNC16(stb_ + soA[1], pA + off16);                             \
        CPASYNC16(stb_ + soA[2], pA + 2 * off16);                         \
        CPASYNC16(stb_ + soA[3], pA + 3 * off16);                         \
        CPASYNC16(stb_ + soA[4], pA + 4 * off16);                         \
        CPASYNC16(stb_ + soA[5], pA + 5 * off16);                         \
        CPASYNC16(stb_ + soA[6], pA + 6 * off16);                         \
        CPASYNC16(stb_ + soA[7], pA + 7 * off16);                         \
        CPASYNC16(stb_ + ATILEB + soA[0], pWh);                           \
        CPASYNC16(stb_ + ATILEB + soA[1], pWh + off16);                   \
        CPASYNC16(stb_ + ATILEB + soA[2], pWh + 2 * off16);               \
        CPASYNC16(stb_ + ATILEB + soA[3], pWh + 3 * off16);               \
        CPASYNC16(stb_ + ATILEB + WTILEB + soA[0], pWl);                  \
        CPASYNC16(stb_ + ATILEB + WTILEB + soA[1], pWl + off16);          \
        CPASYNC16(stb_ + ATILEB + WTILEB + soA[2], pWl + 2 * off16);      \
        CPASYNC16(stb_ + ATILEB + WTILEB + soA[3], pWl + 3 * off16);      \
        asm volatile("cp.async.commit_group;" ::: "memory");              \
        pA += 64; pWh += 64; pWl += 64;                                   \
    } while (0)

    const int wm = wid & 1, wn = wid >> 1;        // 2 x 2 warp grid
    const int m0 = wm * 64, n0 = wn * 32;
    const int lr  = lid & 15;
    const int lkb = (lid >> 4) * 16;

    float acc1[4][4][4];
    uint32_t acc2[4][4][2];
#pragma unroll
    for (int mi = 0; mi < 4; mi++)
#pragma unroll
        for (int nj = 0; nj < 4; nj++) {
#pragma unroll
            for (int q = 0; q < 4; q++) acc1[mi][nj][q] = 0.f;
            acc2[mi][nj][0] = 0u; acc2[mi][nj][1] = 0u;
        }

    uint32_t aoff[4], boff[2];
#pragma unroll
    for (int mi = 0; mi < 4; mi++) {
        int row = m0 + mi * 16 + lr;
        aoff[mi] = (uint32_t)(row * 128) + (uint32_t)(((row & 7) * 16) ^ lkb);
    }
#pragma unroll
    for (int ni = 0; ni < 2; ni++) {
        int row = n0 + ni * 16 + lr;
        boff[ni] = (uint32_t)(row * 128) + (uint32_t)(((row & 7) * 16) ^ lkb);
    }

    LOAD_STAGE(0);
    LOAD_STAGE(1);

    for (int c = 0; c < NCH; c++) {
        if (c + 1 < NCH) asm volatile("cp.async.wait_group 1;" ::: "memory");
        else             asm volatile("cp.async.wait_group 0;" ::: "memory");
        __syncthreads();
        if (c + 2 < NCH) LOAD_STAGE((c + 2) % NSTG);

        uint32_t stb = tb + (uint32_t)(c % NSTG) * STAGEB;
#pragma unroll
        for (int kk = 0; kk < 4; kk++) {
            uint32_t kx = (uint32_t)(kk * 32);
            uint32_t a_f[4][4];
#pragma unroll
            for (int mi = 0; mi < 4; mi++)
                ldsm4(a_f[mi], stb + (aoff[mi] ^ kx));
            uint32_t w_h[2][4], w_l[2][4];
#pragma unroll
            for (int ni = 0; ni < 2; ni++) {
                uint32_t bd = stb + ATILEB + (boff[ni] ^ kx);
                ldsm4(w_h[ni], bd);
                ldsm4(w_l[ni], bd + WTILEB);
            }
#pragma unroll
            for (int mi = 0; mi < 4; mi++)
#pragma unroll
                for (int ni = 0; ni < 2; ni++) {
                    mma16816(acc1[mi][2*ni],    a_f[mi], w_h[ni][0], w_h[ni][2]);
                    mma16816h(acc2[mi][2*ni],   a_f[mi], w_l[ni][0], w_l[ni][2]);
                    mma16816(acc1[mi][2*ni+1],  a_f[mi], w_h[ni][1], w_h[ni][3]);
                    mma16816h(acc2[mi][2*ni+1], a_f[mi], w_l[ni][1], w_l[ni][3]);
                }
        }
    }

    const int er = lid >> 2;
    const int ec = (lid & 3) * 2;
#pragma unroll
    for (int mi = 0; mi < 4; mi++) {
        int grow0 = (int)arow + m0 + mi * 16 + er;
#pragma unroll
        for (int nj = 0; nj < 4; nj++) {
            int gcol = (int)brow + n0 + nj * 8 + ec;
            float2 l0 = __half22float2(*(const __half2*)&acc2[mi][nj][0]);
            float2 l1 = __half22float2(*(const __half2*)&acc2[mi][nj][1]);
            if (gcol + 1 < N) {
                float b0 = __ldg(&bias[gcol]), b1 = __ldg(&bias[gcol + 1]);
                float2 v0 = {acc1[mi][nj][0] + l0.x * RES_INV + b0,
                             acc1[mi][nj][1] + l0.y * RES_INV + b1};
                float2 v1 = {acc1[mi][nj][2] + l1.x * RES_INV + b0,
                             acc1[mi][nj][3] + l1.y * RES_INV + b1};
                *(float2*)&C[(size_t)grow0 * N + gcol] = v0;
                *(float2*)&C[(size_t)(grow0 + 8) * N + gcol] = v1;
            } else if (gcol < N) {
                float b0 = __ldg(&bias[gcol]);
                C[(size_t)grow0 * N + gcol] = acc1[mi][nj][0] + l0.x * RES_INV + b0;
                C[(size_t)(grow0 + 8) * N + gcol] = acc1[mi][nj][2] + l1.x * RES_INV + b0;
            }
        }
    }
#undef LOAD_STAGE
}

// ---------------- fp32 -> fp16 conversions ---------------------------------
__global__ void cvt_fp16_kernel(const float4* __restrict__ src,
                                __half2* __restrict__ dst, size_t n4)
{
    size_t i = (size_t)blockIdx.x * blockDim.x + threadIdx.x;
    if (i >= n4) return;
    float4 v = src[i];
    dst[2*i]   = __floats2half2_rn(v.x, v.y);
    dst[2*i+1] = __floats2half2_rn(v.z, v.w);
}

__global__ void cvt_split_fp16_kernel(const float4* __restrict__ src,
                                      __half2* __restrict__ hi,
                                      __half2* __restrict__ lo,
                                      size_t n4v, size_t n4t)
{
    size_t i = (size_t)blockIdx.x * blockDim.x + threadIdx.x;
    if (i >= n4t) return;
    float4 v = (i < n4v) ? src[i] : make_float4(0.f, 0.f, 0.f, 0.f);
    __half h0 = __float2half_rn(v.x), h1 = __float2half_rn(v.y);
    __half h2 = __float2half_rn(v.z), h3 = __float2half_rn(v.w);
    hi[2*i]   = __halves2half2(h0, h1);
    hi[2*i+1] = __halves2half2(h2, h3);
    lo[2*i]   = __floats2half2_rn((v.x - __half2float(h0)) * RES_SCALE,
                                  (v.y - __half2float(h1)) * RES_SCALE);
    lo[2*i+1] = __floats2half2_rn((v.z - __half2float(h2)) * RES_SCALE,
                                  (v.w - __half2float(h3)) * RES_SCALE);
}

// ---------------- causal depthwise conv (K=4) + SiLU: rolling window -------
// grid (CONVD_/256, Ll/128, Bb), 256 threads. Coalesced, each input read once.
__global__ __launch_bounds__(256) void conv_silu_kernel(
    const float* __restrict__ proj, const float* __restrict__ cw,
    float* __restrict__ xbc)
{
    const int ch = blockIdx.x * 256 + threadIdx.x;     // channel (< 4352)
    const int b  = blockIdx.z;
    const int t0 = blockIdx.y * 128;
    const float* col = proj + (size_t)b * Ll * PROJ_ + INTER_ + ch;
    const float4 w = *(const float4*)&cw[ch * 4];
    float xm3 = 0.f, xm2 = 0.f, xm1 = 0.f;
    if (t0 > 0) {
        xm3 = col[(size_t)(t0 - 3) * PROJ_];
        xm2 = col[(size_t)(t0 - 2) * PROJ_];
        xm1 = col[(size_t)(t0 - 1) * PROJ_];
    }
    float* dst = xbc + ((size_t)(b * Ll + t0)) * CONVD_ + ch;
    const float* srcp = col + (size_t)t0 * PROJ_;
#pragma unroll 4
    for (int k = 0; k < 128; k++) {
        float xc = srcp[(size_t)k * PROJ_];
        float acc = w.x * xm3 + w.y * xm2 + w.z * xm1 + w.w * xc;
        float sg = 1.f / (1.f + expf(-acc));
        dst[(size_t)k * CONVD_] = acc * sg;
        xm3 = xm2; xm2 = xm1; xm1 = xc;
    }
}

// ---------------- P = C * B^T, shared across heads -------------------------
__device__ __constant__ int c_PI[10] = {0,1,1,2,2,2,3,3,3,3};
__device__ __constant__ int c_PJ[10] = {0,0,1,0,1,2,0,1,2,3};

__global__ __launch_bounds__(256, 3) void pmat_kernel(
    const float* __restrict__ xbc, float* __restrict__ P)
{
    const int p = blockIdx.x, c = blockIdx.y, b = blockIdx.z;
    const int i = c_PI[p], j = c_PJ[p];
    const int tid = threadIdx.x;
    extern __shared__ float sm[];
    float* CsT = sm;              // [128][68]
    float* BsT = CsT + 128 * 68;  // [128][68]
    const size_t rowbase = (size_t)(b * Ll + c * CS_);

    for (int idx = tid; idx < 64 * 128; idx += 256) {
        int tl = idx >> 7, n = idx & 127;
        CsT[n * 68 + tl] = xbc[(rowbase + i * 64 + tl) * CONVD_ + (INTER_ + ST_) + n];
        BsT[n * 68 + tl] = xbc[(rowbase + j * 64 + tl) * CONVD_ + INTER_ + n];
    }
    __syncthreads();

    const int tx = tid & 15, ty = tid >> 4;
    const int t0 = ty * 4, s0 = tx * 4;
    float pf[4][4];
#pragma unroll
    for (int r = 0; r < 4; r++)
#pragma unroll
        for (int q = 0; q < 4; q++) pf[r][q] = 0.f;
    for (int n = 0; n < 128; n++) {
        float4 c4 = *(const float4*)&CsT[n * 68 + t0];
        float4 b4 = *(const float4*)&BsT[n * 68 + s0];
        float cr[4] = {c4.x, c4.y, c4.z, c4.w};
        float br[4] = {b4.x, b4.y, b4.z, b4.w};
#pragma unroll
        for (int r = 0; r < 4; r++)
#pragma unroll
            for (int q = 0; q < 4; q++)
                pf[r][q] = fmaf(cr[r], br[q], pf[r][q]);
    }
    float* dst = P + ((size_t)(b * NC_ + c) * CS_) * CS_;
#pragma unroll
    for (int r = 0; r < 4; r++) {
        float4 o = {pf[r][0], pf[r][1], pf[r][2], pf[r][3]};
        *(float4*)&dst[(size_t)(i * 64 + t0 + r) * CS_ + j * 64 + s0] = o;
    }
}

// ---------------- intra-chunk scan: Y_diag + per-chunk states -------------
__global__ __launch_bounds__(256, 2) void scan_intra_kernel(
    const float* __restrict__ proj, const float* __restrict__ xbc,
    const float* __restrict__ gP,
    const float* __restrict__ dt_bias, const float* __restrict__ A_log,
    float* __restrict__ ydiag, float* __restrict__ states,
    float* __restrict__ cumg, float* __restrict__ alast)
{
    const int h = blockIdx.x, c = blockIdx.y, b = blockIdx.z;
    const int tid = threadIdx.x;
    extern __shared__ float sm[];
    float* PsT   = sm;                // [64][68]  (s, t)
    float* xsm   = PsT + 64 * 68;     // [64][68]  (s, p)
    float* Bs    = xsm + 64 * 68;     // [64][132] (s, n)
    float* dsh   = Bs + 64 * 132;     // [256]
    float* cum   = dsh + 256;         // [256]
    float* wlast = cum + 256;         // [256]
    float* Esh   = wlast + 256;       // [64]
    float* Rsh   = Esh + 64;          // [64]

    {
        float Ah = -expf(A_log[h]);
        float v = proj[(size_t)(b * Ll + c * CS_ + tid) * PROJ_ + (INTER_ + CONVD_) + h]
                + dt_bias[h];
        float dtv = (v > 20.f) ? v : log1pf(expf(v));
        dsh[tid] = dtv;
        cum[tid] = Ah * dtv;
    }
    __syncthreads();
    for (int off = 1; off < 256; off <<= 1) {
        float add = (tid >= off) ? cum[tid - off] : 0.f;
        __syncthreads();
        cum[tid] += add;
        __syncthreads();
    }
    cumg[(size_t)(b * NH_ + h) * Ll + c * CS_ + tid] = cum[tid];
    if (tid == 255) alast[(b * NH_ + h) * NC_ + c] = cum[255];
    wlast[tid] = expf(cum[255] - cum[tid]);
    __syncthreads();

    const int tx = tid & 15, ty = tid >> 4;
    const int t0 = ty * 4, p0 = tx * 4;
    float stacc[4][8];
#pragma unroll
    for (int r = 0; r < 4; r++)
#pragma unroll
        for (int q = 0; q < 8; q++) stacc[r][q] = 0.f;

    const size_t rowbase = (size_t)(b * Ll + c * CS_);
    const float* Pblk = gP + ((size_t)(b * NC_ + c) * CS_) * CS_;

    for (int i = 0; i < 4; i++) {
        if (tid < 64) Esh[tid] = expf(cum[i * 64 + tid] - cum[i * 64]);
        float yacc[4][4];
#pragma unroll
        for (int r = 0; r < 4; r++)
#pragma unroll
            for (int q = 0; q < 4; q++) yacc[r][q] = 0.f;

        for (int j = 0; j <= i; j++) {
            __syncthreads();
            for (int idx = tid; idx < 64 * 64; idx += 256) {
                int sl = idx >> 6, p = idx & 63;
                xsm[sl * 68 + p] =
                    xbc[(rowbase + j * 64 + sl) * CONVD_ + h * HD_ + p]
                    * dsh[j * 64 + sl];
            }
            if (j < i && tid < 64)
                Rsh[tid] = expf(cum[i * 64] - cum[j * 64 + tid]);
            if (j == i) {
                for (int idx = tid; idx < 64 * 128; idx += 256) {
                    int sl = idx >> 7, n = idx & 127;
                    Bs[sl * 132 + n] =
                        xbc[(rowbase + j * 64 + sl) * CONVD_ + INTER_ + n];
                }
            }
            __syncthreads();

            if (j == i) {
                int n0 = ty * 8;
                for (int sl = 0; sl < 64; sl++) {
                    float w = wlast[i * 64 + sl];
                    float4 x4 = *(const float4*)&xsm[sl * 68 + p0];
                    float xv[4] = {x4.x * w, x4.y * w, x4.z * w, x4.w * w};
                    float4 b0 = *(const float4*)&Bs[sl * 132 + n0];
                    float4 b1 = *(const float4*)&Bs[sl * 132 + n0 + 4];
                    float bv[8] = {b0.x, b0.y, b0.z, b0.w, b1.x, b1.y, b1.z, b1.w};
#pragma unroll
                    for (int q = 0; q < 8; q++)
#pragma unroll
                        for (int r = 0; r < 4; r++)
                            stacc[r][q] = fmaf(xv[r], bv[q], stacc[r][q]);
                }
                for (int idx = tid; idx < 64 * 64; idx += 256) {
                    int tl = idx >> 6, s = idx & 63;
                    float w = (s <= tl) ? expf(cum[i*64 + tl] - cum[i*64 + s]) : 0.f;
                    PsT[s * 68 + tl] = Pblk[(size_t)(i*64 + tl) * CS_ + i*64 + s] * w;
                }
            } else {
                for (int idx = tid; idx < 64 * 64; idx += 256) {
                    int tl = idx >> 6, s = idx & 63;
                    PsT[s * 68 + tl] = Pblk[(size_t)(i*64 + tl) * CS_ + j*64 + s]
                                       * Esh[tl] * Rsh[s];
                }
            }
            __syncthreads();
            for (int sl = 0; sl < 64; sl++) {
                float4 x4 = *(const float4*)&xsm[sl * 68 + p0];
                float4 pw = *(const float4*)&PsT[sl * 68 + t0];
                float pr[4] = {pw.x, pw.y, pw.z, pw.w};
#pragma unroll
                for (int r = 0; r < 4; r++) {
                    yacc[r][0] = fmaf(pr[r], x4.x, yacc[r][0]);
                    yacc[r][1] = fmaf(pr[r], x4.y, yacc[r][1]);
                    yacc[r][2] = fmaf(pr[r], x4.z, yacc[r][2]);
                    yacc[r][3] = fmaf(pr[r], x4.w, yacc[r][3]);
                }
            }
        }
        {
#pragma unroll
            for (int r = 0; r < 4; r++) {
                size_t tg = rowbase + i * 64 + t0 + r;
                float4 o = {yacc[r][0], yacc[r][1], yacc[r][2], yacc[r][3]};
                *(float4*)&ydiag[(tg * NH_ + h) * HD_ + p0] = o;
            }
        }
    }
    {
        int n0 = ty * 8;
        size_t base = ((size_t)((b * NC_ + c) * NH_ + h)) * HD_;
#pragma unroll
        for (int r = 0; r < 4; r++) {
            float4 o0 = {stacc[r][0], stacc[r][1], stacc[r][2], stacc[r][3]};
            float4 o1 = {stacc[r][4], stacc[r][5], stacc[r][6], stacc[r][7]};
            float* dst = states + (base + p0 + r) * ST_ + n0;
            *(float4*)dst = o0;
            *(float4*)(dst + 4) = o1;
        }
    }
}

// ---------------- inter-chunk recurrence -----------------------------------
__global__ void interchunk_kernel(const float* __restrict__ states,
                                  const float* __restrict__ alast,
                                  float* __restrict__ prev)
{
    int bh = blockIdx.x;
    int b = bh >> 6, h = bh & 63;
    float dec[NC_];
#pragma unroll
    for (int c = 0; c < NC_; c++)
        dec[c] = expf(alast[(b * NH_ + h) * NC_ + c]);
    for (int e = threadIdx.x; e < HD_ * ST_; e += 256) {
        float run = 0.f;
#pragma unroll
        for (int c = 0; c < NC_; c++) {
            size_t idx = ((size_t)((b * NC_ + c) * NH_ + h)) * (HD_ * ST_) + e;
            prev[idx] = run;
            run = fmaf(run, dec[c] - 1.f, run);
            run = run + states[idx];
        }
    }
}

// ---------------- Y_off + D-skip, accumulate into y ------------------------
__global__ __launch_bounds__(256, 3) void scan_off_kernel(
    const float* __restrict__ xbc, const float* __restrict__ cumg,
    const float* __restrict__ prev, const float* __restrict__ Dv,
    float* __restrict__ y)
{
    const int h = blockIdx.x, c = blockIdx.y, b = blockIdx.z;
    const int tid = threadIdx.x;
    extern __shared__ float sm[];
    float* pvsT = sm;                  // [128][68]  (n, p)
    float* CsT  = pvsT + 128 * 68;     // [128][68]  (n, t)
    float* esh  = CsT + 128 * 68;      // [256]
    size_t sbase = ((size_t)((b * NC_ + c) * NH_ + h)) * (HD_ * ST_);
    for (int idx = tid; idx < 64 * 128; idx += 256) {
        int p = idx >> 7, n = idx & 127;
        pvsT[n * 68 + p] = prev[sbase + idx];
    }
    esh[tid] = expf(cumg[(size_t)(b * NH_ + h) * Ll + c * CS_ + tid]);
    const float Dh = Dv[h];
    const int tx = tid & 15, ty = tid >> 4;
    const size_t rowbase = (size_t)(b * Ll + c * CS_);
    for (int ti = 0; ti < 4; ti++) {
        __syncthreads();
        for (int idx = tid; idx < 64 * 128; idx += 256) {
            int tl = idx >> 7, n = idx & 127;
            CsT[n * 68 + tl] =
                xbc[(rowbase + ti * 64 + tl) * CONVD_ + (INTER_ + ST_) + n];
        }
        __syncthreads();
        int t0 = ty * 4, p0 = tx * 4;
        float acc[4][4];
#pragma unroll
        for (int r = 0; r < 4; r++)
#pragma unroll
            for (int q = 0; q < 4; q++) acc[r][q] = 0.f;
        for (int n = 0; n < 128; n++) {
            float4 c4 = *(const float4*)&CsT[n * 68 + t0];
            float4 p4 = *(const float4*)&pvsT[n * 68 + p0];
            float cr[4] = {c4.x, c4.y, c4.z, c4.w};
            float pv[4] = {p4.x, p4.y, p4.z, p4.w};
#pragma unroll
            for (int r = 0; r < 4; r++)
#pragma unroll
                for (int q = 0; q < 4; q++)
                    acc[r][q] = fmaf(cr[r], pv[q], acc[r][q]);
        }
#pragma unroll
        for (int r = 0; r < 4; r++) {
            size_t tg = rowbase + ti * 64 + t0 + r;
            float e = esh[ti * 64 + t0 + r];
            float* yp = y + (tg * NH_ + h) * HD_ + p0;
            float4 yv = *(float4*)yp;
            const float4 xv = *(const float4*)&xbc[tg * CONVD_ + h * HD_ + p0];
            yv.x += acc[r][0] * e + Dh * xv.x;
            yv.y += acc[r][1] * e + Dh * xv.y;
            yv.z += acc[r][2] * e + Dh * xv.z;
            yv.w += acc[r][3] * e + Dh * xv.w;
            *(float4*)yp = yv;
        }
    }
}

// ---------------- gated RMSNorm -> fp16 A for GEMM2 ------------------------
__global__ __launch_bounds__(256) void gated_norm_kernel(
    const float* __restrict__ proj, const float* __restrict__ y,
    const float* __restrict__ nw, __half* __restrict__ gf)
{
    int row = blockIdx.x;
    int tid = threadIdx.x;
    float gv[16];
    float ss = 0.f;
    const float* yr = y + (size_t)row * INTER_;
    const float* gr = proj + (size_t)row * PROJ_;
#pragma unroll
    for (int k = 0; k < 16; k++) {
        int idx = tid + k * 256;
        float gt = gr[idx];
        float s = 1.f / (1.f + expf(-gt));
        float v = yr[idx] * gt * s;
        gv[k] = v;
        ss = fmaf(v, v, ss);
    }
    __shared__ float red[256];
    red[tid] = ss;
    __syncthreads();
    for (int off = 128; off > 0; off >>= 1) {
        if (tid < off) red[tid] += red[tid + off];
        __syncthreads();
    }
    float scale = rsqrtf(red[0] / (float)INTER_ + 1e-5f);
#pragma unroll
    for (int k = 0; k < 16; k++) {
        int idx = tid + k * 256;
        gf[(size_t)row * INTER_ + idx] = __float2half_rn(gv[k] * scale * nw[idx]);
    }
}

// ---------------- launch ----------------------------------------------------
extern "C" void kernel_launch(void* const* d_in, const int* in_sizes, int n_in,
                              void* d_out, int out_size)
{
    const float* hidden  = (const float*)d_in[0];
    const float* in_w    = (const float*)d_in[1];
    const float* in_b    = (const float*)d_in[2];
    const float* conv_w  = (const float*)d_in[3];
    const float* dt_bias = (const float*)d_in[4];
    const float* A_log   = (const float*)d_in[5];
    const float* Dv      = (const float*)d_in[6];
    const float* norm_w  = (const float*)d_in[7];
    const float* out_w   = (const float*)d_in[8];
    const float* out_b   = (const float*)d_in[9];
    float* out = (float*)d_out;

    float *proj, *xbc, *y, *states, *prev, *cum, *al, *Pm;
    __half *Af, *W1h, *W1l, *W2h, *W2l;
    cudaGetSymbolAddress((void**)&proj,   g_proj);
    cudaGetSymbolAddress((void**)&xbc,    g_xbc);
    cudaGetSymbolAddress((void**)&y,      g_y);
    cudaGetSymbolAddress((void**)&states, g_states);
    cudaGetSymbolAddress((void**)&prev,   g_prev);
    cudaGetSymbolAddress((void**)&cum,    g_cum);
    cudaGetSymbolAddress((void**)&al,     g_alast);
    cudaGetSymbolAddress((void**)&Pm,     g_P);
    cudaGetSymbolAddress((void**)&Af,     g_Af);
    cudaGetSymbolAddress((void**)&W1h,    g_W1h);
    cudaGetSymbolAddress((void**)&W1l,    g_W1l);
    cudaGetSymbolAddress((void**)&W2h,    g_W2h);
    cudaGetSymbolAddress((void**)&W2l,    g_W2l);

    const int SMEM_PMAT  = (128 * 68 * 2) * 4;
    const int SMEM_INTRA = (64*68*2 + 64*132 + 256*3 + 128) * 4;
    const int SMEM_OFF   = (128*68*2 + 256) * 4;
    cudaFuncSetAttribute(pmat_kernel,
                         cudaFuncAttributeMaxDynamicSharedMemorySize, SMEM_PMAT);
    cudaFuncSetAttribute(scan_intra_kernel,
                         cudaFuncAttributeMaxDynamicSharedMemorySize, SMEM_INTRA);
    cudaFuncSetAttribute(scan_off_kernel,
                         cudaFuncAttributeMaxDynamicSharedMemorySize, SMEM_OFF);
    cudaFuncSetAttribute(tc_gemm_bias,
                         cudaFuncAttributeMaxDynamicSharedMemorySize, GSMEM);

    // 0. fp16 conversions
    {
        size_t n4 = (size_t)MT * HIDDEN_ / 4;
        cvt_fp16_kernel<<<(int)((n4 + 255) / 256), 256>>>(
            (const float4*)hidden, (__half2*)Af, n4);
        size_t n4v = (size_t)PROJ_ * HIDDEN_ / 4, n4t = (size_t)NP1 * HIDDEN_ / 4;
        cvt_split_fp16_kernel<<<(int)((n4t + 255) / 256), 256>>>(
            (const float4*)in_w, (__half2*)W1h, (__half2*)W1l, n4v, n4t);
        n4 = (size_t)HIDDEN_ * INTER_ / 4;
        cvt_split_fp16_kernel<<<(int)((n4 + 255) / 256), 256>>>(
            (const float4*)out_w, (__half2*)W2h, (__half2*)W2l, n4, n4);
    }

    // 1. in_proj GEMM + bias (2-pass fp16 mma.sync, 64x32 warp tiles)
    tc_gemm_bias<<<dim3(NP1 / 64, MT / 128), 128, GSMEM>>>(
        Af, W1h, W1l, in_b, proj, PROJ_, HIDDEN_);

    // 2. causal depthwise conv + SiLU (rolling window)
    conv_silu_kernel<<<dim3(CONVD_ / 256, Ll / 128, Bb), 256>>>(proj, conv_w, xbc);

    // 2b. shared P = C * B^T per (b, chunk)
    pmat_kernel<<<dim3(10, NC_, Bb), 256, SMEM_PMAT>>>(xbc, Pm);

    // 3. intra-chunk scan (per head, reusing P)
    scan_intra_kernel<<<dim3(NH_, NC_, Bb), 256, SMEM_INTRA>>>(
        proj, xbc, Pm, dt_bias, A_log, y, states, cum, al);

    // 4. inter-chunk recurrence
    interchunk_kernel<<<Bb * NH_, 256>>>(states, al, prev);

    // 5. inter-chunk output contribution + D skip
    scan_off_kernel<<<dim3(NH_, NC_, Bb), 256, SMEM_OFF>>>(xbc, cum, prev, Dv, y);

    // 6. gated RMSNorm -> fp16 A for GEMM2 (reuses Af)
    gated_norm_kernel<<<MT, 256>>>(proj, y, norm_w, Af);

    // 7. out_proj GEMM + bias
    tc_gemm_bias<<<dim3(HIDDEN_ / 64, MT / 128), 128, GSMEM>>>(
        Af, W2h, W2l, out_b, out, HIDDEN_, INTER_);
}

// round 9
// speedup vs baseline: 1.3496x; 1.3496x over previous
#include <cuda_runtime.h>
#include <cuda_bf16.h>
#include <cuda_fp16.h>
#include <math.h>
#include <cstdint>

#define Bb      2
#define Ll      2048
#define HIDDEN_ 2048
#define PROJ_   8512
#define INTER_  4096
#define CONVD_  4352
#define NH_     64
#define HD_     64
#define ST_     128
#define NC_     8
#define CS_     256
#define MT      (Bb*Ll)      // 4096
#define NP1     8576

// ---------------- static scratch ----------------
__device__ float g_proj  [(size_t)MT*PROJ_];
__device__ float g_xbc   [(size_t)MT*CONVD_];
__device__ float g_y     [(size_t)MT*INTER_];
__device__ float g_states[(size_t)Bb*NC_*NH_*HD_*ST_];
__device__ float g_prev  [(size_t)Bb*NC_*NH_*HD_*ST_];
__device__ float g_cum   [(size_t)Bb*NH_*Ll];
__device__ float g_alast [(size_t)Bb*NH_*NC_];
__device__ float g_P     [(size_t)Bb*NC_*CS_*CS_];
__device__ __half g_Af [(size_t)MT*INTER_];
__device__ __half g_W1 [(size_t)NP1*HIDDEN_];
__device__ __half g_W2 [(size_t)HIDDEN_*INTER_];

// ======================= warp-MMA helpers ====================
__device__ __forceinline__ uint32_t cvta_smem(const void* p) {
    uint32_t a;
    asm("{ .reg .u64 t; cvta.to.shared.u64 t, %1; cvt.u32.u64 %0, t; }"
        : "=r"(a) : "l"(p));
    return a;
}

__device__ __forceinline__ void ldsm4(uint32_t* r, uint32_t addr) {
    asm volatile("ldmatrix.sync.aligned.m8n8.x4.shared.b16 {%0,%1,%2,%3}, [%4];"
                 : "=r"(r[0]), "=r"(r[1]), "=r"(r[2]), "=r"(r[3]) : "r"(addr));
}

__device__ __forceinline__ void mma16816(float* c, const uint32_t* a,
                                         uint32_t b0, uint32_t b1) {
    asm volatile(
        "mma.sync.aligned.m16n8k16.row.col.f32.f16.f16.f32 "
        "{%0,%1,%2,%3}, {%4,%5,%6,%7}, {%8,%9}, {%0,%1,%2,%3};"
        : "+f"(c[0]), "+f"(c[1]), "+f"(c[2]), "+f"(c[3])
        : "r"(a[0]), "r"(a[1]), "r"(a[2]), "r"(a[3]), "r"(b0), "r"(b1));
}

#define CPASYNC16(sa, ga) \
    asm volatile("cp.async.cg.shared.global [%0], [%1], 16;" :: "r"(sa), "l"(ga) : "memory")

// GEMM tiling: BM=128, BN=128, BK=64, 256 threads, 2 CTAs/SM, 3 stages
#define ATILEB 16384u
#define STAGEB 32768u
#define NSTG   3
#define GSMEM  (1024 + NSTG*32768)   // 99328

// =========================================================================
// single-pass fp16 tensor-core GEMM: C = A*W^T + bias
// 8 warps in 4(M) x 2(N) grid, warp tile 32(M) x 64(N): mma:ldsm = 2.67
// =========================================================================
__global__ __launch_bounds__(256, 2)
void tc_gemm_bias(
    const __half* __restrict__ A, const __half* __restrict__ W,
    const float* __restrict__ bias, float* __restrict__ C, int N, int K)
{
    extern __shared__ __align__(128) char smem[];
    const int tid = threadIdx.x;
    const int lid = tid & 31, wid = tid >> 5;
    uint32_t sb = cvta_smem(smem);
    uint32_t tb = (sb + 1023u) & ~1023u;

    const size_t arow = (size_t)blockIdx.y * 128;
    const size_t brow = (size_t)blockIdx.x * 128;
    const int NCH = K >> 6;

    // ---- loader: 256 threads, 8 cp.async/thread/stage (A 16KB + W 16KB) ----
    const int seg = tid & 7, r0 = tid >> 3;       // r0: 0..31
    uint32_t so[4];
#pragma unroll
    for (int k = 0; k < 4; k++) {
        uint32_t off = (uint32_t)((r0 + 32 * k) * 128 + seg * 16);
        so[k] = off ^ ((off >> 3) & 0x70);
    }
    const __half* pA = A + (arow + r0) * (size_t)K + (seg << 3);
    const __half* pW = W + (brow + r0) * (size_t)K + (seg << 3);
    const size_t off32 = (size_t)32 * K;

#define LOAD_STAGE(s)                                                     \
    do {                                                                  \
        uint32_t stb_ = tb + (uint32_t)(s) * STAGEB;                      \
        CPASYNC16(stb_ + so[0], pA);                                      \
        CPASYNC16(stb_ + so[1], pA + off32);                              \
        CPASYNC16(stb_ + so[2], pA + 2 * off32);                          \
        CPASYNC16(stb_ + so[3], pA + 3 * off32);                          \
        CPASYNC16(stb_ + ATILEB + so[0], pW);                             \
        CPASYNC16(stb_ + ATILEB + so[1], pW + off32);                     \
        CPASYNC16(stb_ + ATILEB + so[2], pW + 2 * off32);                 \
        CPASYNC16(stb_ + ATILEB + so[3], pW + 3 * off32);                 \
        asm volatile("cp.async.commit_group;" ::: "memory");              \
        pA += 64; pW += 64;                                               \
    } while (0)

    const int wm = wid & 3, wn = wid >> 2;        // 4 x 2 warp grid
    const int m0 = wm * 32, n0 = wn * 64;
    const int lr  = lid & 15;
    const int lkb = (lid >> 4) * 16;

    float acc[2][8][4];
#pragma unroll
    for (int mi = 0; mi < 2; mi++)
#pragma unroll
        for (int nj = 0; nj < 8; nj++)
#pragma unroll
            for (int q = 0; q < 4; q++) acc[mi][nj][q] = 0.f;

    uint32_t aoff[2], boff[4];
#pragma unroll
    for (int mi = 0; mi < 2; mi++) {
        int row = m0 + mi * 16 + lr;
        aoff[mi] = (uint32_t)(row * 128) + (uint32_t)(((row & 7) * 16) ^ lkb);
    }
#pragma unroll
    for (int ni = 0; ni < 4; ni++) {
        int row = n0 + ni * 16 + lr;
        boff[ni] = (uint32_t)(row * 128) + (uint32_t)(((row & 7) * 16) ^ lkb);
    }

    LOAD_STAGE(0);
    LOAD_STAGE(1);

    for (int c = 0; c < NCH; c++) {
        if (c + 1 < NCH) asm volatile("cp.async.wait_group 1;" ::: "memory");
        else             asm volatile("cp.async.wait_group 0;" ::: "memory");
        __syncthreads();
        if (c + 2 < NCH) LOAD_STAGE((c + 2) % NSTG);

        uint32_t stb = tb + (uint32_t)(c % NSTG) * STAGEB;
#pragma unroll
        for (int kk = 0; kk < 4; kk++) {
            uint32_t kx = (uint32_t)(kk * 32);
            uint32_t a_f[2][4];
#pragma unroll
            for (int mi = 0; mi < 2; mi++)
                ldsm4(a_f[mi], stb + (aoff[mi] ^ kx));
            uint32_t w_f[4][4];
#pragma unroll
            for (int ni = 0; ni < 4; ni++)
                ldsm4(w_f[ni], stb + ATILEB + (boff[ni] ^ kx));
#pragma unroll
            for (int mi = 0; mi < 2; mi++)
#pragma unroll
                for (int ni = 0; ni < 4; ni++) {
                    mma16816(acc[mi][2*ni],   a_f[mi], w_f[ni][0], w_f[ni][2]);
                    mma16816(acc[mi][2*ni+1], a_f[mi], w_f[ni][1], w_f[ni][3]);
                }
        }
    }

    const int er = lid >> 2;
    const int ec = (lid & 3) * 2;
#pragma unroll
    for (int mi = 0; mi < 2; mi++) {
        int grow0 = (int)arow + m0 + mi * 16 + er;
#pragma unroll
        for (int nj = 0; nj < 8; nj++) {
            int gcol = (int)brow + n0 + nj * 8 + ec;
            if (gcol + 1 < N) {
                float b0 = __ldg(&bias[gcol]), b1 = __ldg(&bias[gcol + 1]);
                float2 v0 = {acc[mi][nj][0] + b0, acc[mi][nj][1] + b1};
                float2 v1 = {acc[mi][nj][2] + b0, acc[mi][nj][3] + b1};
                *(float2*)&C[(size_t)grow0 * N + gcol] = v0;
                *(float2*)&C[(size_t)(grow0 + 8) * N + gcol] = v1;
            } else if (gcol < N) {
                float b0 = __ldg(&bias[gcol]);
                C[(size_t)grow0 * N + gcol] = acc[mi][nj][0] + b0;
                C[(size_t)(grow0 + 8) * N + gcol] = acc[mi][nj][2] + b0;
            }
        }
    }
#undef LOAD_STAGE
}

// ---------------- fp32 -> fp16 conversions ---------------------------------
__global__ void cvt_fp16_kernel(const float4* __restrict__ src,
                                __half2* __restrict__ dst, size_t n4)
{
    size_t i = (size_t)blockIdx.x * blockDim.x + threadIdx.x;
    if (i >= n4) return;
    float4 v = src[i];
    dst[2*i]   = __floats2half2_rn(v.x, v.y);
    dst[2*i+1] = __floats2half2_rn(v.z, v.w);
}

__global__ void cvt_fp16_pad_kernel(const float4* __restrict__ src,
                                    __half2* __restrict__ dst,
                                    size_t n4v, size_t n4t)
{
    size_t i = (size_t)blockIdx.x * blockDim.x + threadIdx.x;
    if (i >= n4t) return;
    float4 v = (i < n4v) ? src[i] : make_float4(0.f, 0.f, 0.f, 0.f);
    dst[2*i]   = __floats2half2_rn(v.x, v.y);
    dst[2*i+1] = __floats2half2_rn(v.z, v.w);
}

// ---------------- causal depthwise conv (K=4) + SiLU: rolling window -------
__global__ __launch_bounds__(256) void conv_silu_kernel(
    const float* __restrict__ proj, const float* __restrict__ cw,
    float* __restrict__ xbc)
{
    const int ch = blockIdx.x * 256 + threadIdx.x;
    const int b  = blockIdx.z;
    const int t0 = blockIdx.y * 128;
    const float* col = proj + (size_t)b * Ll * PROJ_ + INTER_ + ch;
    const float4 w = *(const float4*)&cw[ch * 4];
    float xm3 = 0.f, xm2 = 0.f, xm1 = 0.f;
    if (t0 > 0) {
        xm3 = col[(size_t)(t0 - 3) * PROJ_];
        xm2 = col[(size_t)(t0 - 2) * PROJ_];
        xm1 = col[(size_t)(t0 - 1) * PROJ_];
    }
    float* dst = xbc + ((size_t)(b * Ll + t0)) * CONVD_ + ch;
    const float* srcp = col + (size_t)t0 * PROJ_;
#pragma unroll 4
    for (int k = 0; k < 128; k++) {
        float xc = srcp[(size_t)k * PROJ_];
        float acc = w.x * xm3 + w.y * xm2 + w.z * xm1 + w.w * xc;
        float sg = 1.f / (1.f + expf(-acc));
        dst[(size_t)k * CONVD_] = acc * sg;
        xm3 = xm2; xm2 = xm1; xm1 = xc;
    }
}

// ---------------- P = C * B^T, shared across heads -------------------------
__device__ __constant__ int c_PI[10] = {0,1,1,2,2,2,3,3,3,3};
__device__ __constant__ int c_PJ[10] = {0,0,1,0,1,2,0,1,2,3};

__global__ __launch_bounds__(256, 3) void pmat_kernel(
    const float* __restrict__ xbc, float* __restrict__ P)
{
    const int p = blockIdx.x, c = blockIdx.y, b = blockIdx.z;
    const int i = c_PI[p], j = c_PJ[p];
    const int tid = threadIdx.x;
    extern __shared__ float sm[];
    float* CsT = sm;              // [128][68]
    float* BsT = CsT + 128 * 68;  // [128][68]
    const size_t rowbase = (size_t)(b * Ll + c * CS_);

    for (int idx = tid; idx < 64 * 128; idx += 256) {
        int tl = idx >> 7, n = idx & 127;
        CsT[n * 68 + tl] = xbc[(rowbase + i * 64 + tl) * CONVD_ + (INTER_ + ST_) + n];
        BsT[n * 68 + tl] = xbc[(rowbase + j * 64 + tl) * CONVD_ + INTER_ + n];
    }
    __syncthreads();

    const int tx = tid & 15, ty = tid >> 4;
    const int t0 = ty * 4, s0 = tx * 4;
    float pf[4][4];
#pragma unroll
    for (int r = 0; r < 4; r++)
#pragma unroll
        for (int q = 0; q < 4; q++) pf[r][q] = 0.f;
    for (int n = 0; n < 128; n++) {
        float4 c4 = *(const float4*)&CsT[n * 68 + t0];
        float4 b4 = *(const float4*)&BsT[n * 68 + s0];
        float cr[4] = {c4.x, c4.y, c4.z, c4.w};
        float br[4] = {b4.x, b4.y, b4.z, b4.w};
#pragma unroll
        for (int r = 0; r < 4; r++)
#pragma unroll
            for (int q = 0; q < 4; q++)
                pf[r][q] = fmaf(cr[r], br[q], pf[r][q]);
    }
    float* dst = P + ((size_t)(b * NC_ + c) * CS_) * CS_;
#pragma unroll
    for (int r = 0; r < 4; r++) {
        float4 o = {pf[r][0], pf[r][1], pf[r][2], pf[r][3]};
        *(float4*)&dst[(size_t)(i * 64 + t0 + r) * CS_ + j * 64 + s0] = o;
    }
}

// ---------------- intra-chunk scan: Y_diag + per-chunk states -------------
__global__ __launch_bounds__(256, 2) void scan_intra_kernel(
    const float* __restrict__ proj, const float* __restrict__ xbc,
    const float* __restrict__ gP,
    const float* __restrict__ dt_bias, const float* __restrict__ A_log,
    float* __restrict__ ydiag, float* __restrict__ states,
    float* __restrict__ cumg, float* __restrict__ alast)
{
    const int h = blockIdx.x, c = blockIdx.y, b = blockIdx.z;
    const int tid = threadIdx.x;
    extern __shared__ float sm[];
    float* PsT   = sm;                // [64][68]
    float* xsm   = PsT + 64 * 68;     // [64][68]
    float* Bs    = xsm + 64 * 68;     // [64][132]
    float* dsh   = Bs + 64 * 132;     // [256]
    float* cum   = dsh + 256;         // [256]
    float* wlast = cum + 256;         // [256]
    float* Esh   = wlast + 256;       // [64]
    float* Rsh   = Esh + 64;          // [64]

    {
        float Ah = -expf(A_log[h]);
        float v = proj[(size_t)(b * Ll + c * CS_ + tid) * PROJ_ + (INTER_ + CONVD_) + h]
                + dt_bias[h];
        float dtv = (v > 20.f) ? v : log1pf(expf(v));
        dsh[tid] = dtv;
        cum[tid] = Ah * dtv;
    }
    __syncthreads();
    for (int off = 1; off < 256; off <<= 1) {
        float add = (tid >= off) ? cum[tid - off] : 0.f;
        __syncthreads();
        cum[tid] += add;
        __syncthreads();
    }
    cumg[(size_t)(b * NH_ + h) * Ll + c * CS_ + tid] = cum[tid];
    if (tid == 255) alast[(b * NH_ + h) * NC_ + c] = cum[255];
    wlast[tid] = expf(cum[255] - cum[tid]);
    __syncthreads();

    const int tx = tid & 15, ty = tid >> 4;
    const int t0 = ty * 4, p0 = tx * 4;
    float stacc[4][8];
#pragma unroll
    for (int r = 0; r < 4; r++)
#pragma unroll
        for (int q = 0; q < 8; q++) stacc[r][q] = 0.f;

    const size_t rowbase = (size_t)(b * Ll + c * CS_);
    const float* Pblk = gP + ((size_t)(b * NC_ + c) * CS_) * CS_;

    for (int i = 0; i < 4; i++) {
        if (tid < 64) Esh[tid] = expf(cum[i * 64 + tid] - cum[i * 64]);
        float yacc[4][4];
#pragma unroll
        for (int r = 0; r < 4; r++)
#pragma unroll
            for (int q = 0; q < 4; q++) yacc[r][q] = 0.f;

        for (int j = 0; j <= i; j++) {
            __syncthreads();
            for (int idx = tid; idx < 64 * 64; idx += 256) {
                int sl = idx >> 6, p = idx & 63;
                xsm[sl * 68 + p] =
                    xbc[(rowbase + j * 64 + sl) * CONVD_ + h * HD_ + p]
                    * dsh[j * 64 + sl];
            }
            if (j < i && tid < 64)
                Rsh[tid] = expf(cum[i * 64] - cum[j * 64 + tid]);
            if (j == i) {
                for (int idx = tid; idx < 64 * 128; idx += 256) {
                    int sl = idx >> 7, n = idx & 127;
                    Bs[sl * 132 + n] =
                        xbc[(rowbase + j * 64 + sl) * CONVD_ + INTER_ + n];
                }
            }
            __syncthreads();

            if (j == i) {
                int n0 = ty * 8;
                for (int sl = 0; sl < 64; sl++) {
                    float w = wlast[i * 64 + sl];
                    float4 x4 = *(const float4*)&xsm[sl * 68 + p0];
                    float xv[4] = {x4.x * w, x4.y * w, x4.z * w, x4.w * w};
                    float4 b0 = *(const float4*)&Bs[sl * 132 + n0];
                    float4 b1 = *(const float4*)&Bs[sl * 132 + n0 + 4];
                    float bv[8] = {b0.x, b0.y, b0.z, b0.w, b1.x, b1.y, b1.z, b1.w};
#pragma unroll
                    for (int q = 0; q < 8; q++)
#pragma unroll
                        for (int r = 0; r < 4; r++)
                            stacc[r][q] = fmaf(xv[r], bv[q], stacc[r][q]);
                }
                for (int idx = tid; idx < 64 * 64; idx += 256) {
                    int tl = idx >> 6, s = idx & 63;
                    float w = (s <= tl) ? expf(cum[i*64 + tl] - cum[i*64 + s]) : 0.f;
                    PsT[s * 68 + tl] = Pblk[(size_t)(i*64 + tl) * CS_ + i*64 + s] * w;
                }
            } else {
                for (int idx = tid; idx < 64 * 64; idx += 256) {
                    int tl = idx >> 6, s = idx & 63;
                    PsT[s * 68 + tl] = Pblk[(size_t)(i*64 + tl) * CS_ + j*64 + s]
                                       * Esh[tl] * Rsh[s];
                }
            }
            __syncthreads();
            for (int sl = 0; sl < 64; sl++) {
                float4 x4 = *(const float4*)&xsm[sl * 68 + p0];
                float4 pw = *(const float4*)&PsT[sl * 68 + t0];
                float pr[4] = {pw.x, pw.y, pw.z, pw.w};
#pragma unroll
                for (int r = 0; r < 4; r++) {
                    yacc[r][0] = fmaf(pr[r], x4.x, yacc[r][0]);
                    yacc[r][1] = fmaf(pr[r], x4.y, yacc[r][1]);
                    yacc[r][2] = fmaf(pr[r], x4.z, yacc[r][2]);
                    yacc[r][3] = fmaf(pr[r], x4.w, yacc[r][3]);
                }
            }
        }
        {
#pragma unroll
            for (int r = 0; r < 4; r++) {
                size_t tg = rowbase + i * 64 + t0 + r;
                float4 o = {yacc[r][0], yacc[r][1], yacc[r][2], yacc[r][3]};
                *(float4*)&ydiag[(tg * NH_ + h) * HD_ + p0] = o;
            }
        }
    }
    {
        int n0 = ty * 8;
        size_t base = ((size_t)((b * NC_ + c) * NH_ + h)) * HD_;
#pragma unroll
        for (int r = 0; r < 4; r++) {
            float4 o0 = {stacc[r][0], stacc[r][1], stacc[r][2], stacc[r][3]};
            float4 o1 = {stacc[r][4], stacc[r][5], stacc[r][6], stacc[r][7]};
            float* dst = states + (base + p0 + r) * ST_ + n0;
            *(float4*)dst = o0;
            *(float4*)(dst + 4) = o1;
        }
    }
}

// ---------------- inter-chunk recurrence -----------------------------------
__global__ void interchunk_kernel(const float* __restrict__ states,
                                  const float* __restrict__ alast,
                                  float* __restrict__ prev)
{
    int bh = blockIdx.x;
    int b = bh >> 6, h = bh & 63;
    float dec[NC_];
#pragma unroll
    for (int c = 0; c < NC_; c++)
        dec[c] = expf(alast[(b * NH_ + h) * NC_ + c]);
    for (int e = threadIdx.x; e < HD_ * ST_; e += 256) {
        float run = 0.f;
#pragma unroll
        for (int c = 0; c < NC_; c++) {
            size_t idx = ((size_t)((b * NC_ + c) * NH_ + h)) * (HD_ * ST_) + e;
            prev[idx] = run;
            run = fmaf(run, dec[c] - 1.f, run);
            run = run + states[idx];
        }
    }
}

// ---------------- Y_off + D-skip, accumulate into y ------------------------
__global__ __launch_bounds__(256, 3) void scan_off_kernel(
    const float* __restrict__ xbc, const float* __restrict__ cumg,
    const float* __restrict__ prev, const float* __restrict__ Dv,
    float* __restrict__ y)
{
    const int h = blockIdx.x, c = blockIdx.y, b = blockIdx.z;
    const int tid = threadIdx.x;
    extern __shared__ float sm[];
    float* pvsT = sm;                  // [128][68]
    float* CsT  = pvsT + 128 * 68;     // [128][68]
    float* esh  = CsT + 128 * 68;      // [256]
    size_t sbase = ((size_t)((b * NC_ + c) * NH_ + h)) * (HD_ * ST_);
    for (int idx = tid; idx < 64 * 128; idx += 256) {
        int p = idx >> 7, n = idx & 127;
        pvsT[n * 68 + p] = prev[sbase + idx];
    }
    esh[tid] = expf(cumg[(size_t)(b * NH_ + h) * Ll + c * CS_ + tid]);
    const float Dh = Dv[h];
    const int tx = tid & 15, ty = tid >> 4;
    const size_t rowbase = (size_t)(b * Ll + c * CS_);
    for (int ti = 0; ti < 4; ti++) {
        __syncthreads();
        for (int idx = tid; idx < 64 * 128; idx += 256) {
            int tl = idx >> 7, n = idx & 127;
            CsT[n * 68 + tl] =
                xbc[(rowbase + ti * 64 + tl) * CONVD_ + (INTER_ + ST_) + n];
        }
        __syncthreads();
        int t0 = ty * 4, p0 = tx * 4;
        float acc[4][4];
#pragma unroll
        for (int r = 0; r < 4; r++)
#pragma unroll
            for (int q = 0; q < 4; q++) acc[r][q] = 0.f;
        for (int n = 0; n < 128; n++) {
            float4 c4 = *(const float4*)&CsT[n * 68 + t0];
            float4 p4 = *(const float4*)&pvsT[n * 68 + p0];
            float cr[4] = {c4.x, c4.y, c4.z, c4.w};
            float pv[4] = {p4.x, p4.y, p4.z, p4.w};
#pragma unroll
            for (int r = 0; r < 4; r++)
#pragma unroll
                for (int q = 0; q < 4; q++)
                    acc[r][q] = fmaf(cr[r], pv[q], acc[r][q]);
        }
#pragma unroll
        for (int r = 0; r < 4; r++) {
            size_t tg = rowbase + ti * 64 + t0 + r;
            float e = esh[ti * 64 + t0 + r];
            float* yp = y + (tg * NH_ + h) * HD_ + p0;
            float4 yv = *(float4*)yp;
            const float4 xv = *(const float4*)&xbc[tg * CONVD_ + h * HD_ + p0];
            yv.x += acc[r][0] * e + Dh * xv.x;
            yv.y += acc[r][1] * e + Dh * xv.y;
            yv.z += acc[r][2] * e + Dh * xv.z;
            yv.w += acc[r][3] * e + Dh * xv.w;
            *(float4*)yp = yv;
        }
    }
}

// ---------------- gated RMSNorm -> fp16 A for GEMM2 ------------------------
__global__ __launch_bounds__(256) void gated_norm_kernel(
    const float* __restrict__ proj, const float* __restrict__ y,
    const float* __restrict__ nw, __half* __restrict__ gf)
{
    int row = blockIdx.x;
    int tid = threadIdx.x;
    float gv[16];
    float ss = 0.f;
    const float* yr = y + (size_t)row * INTER_;
    const float* gr = proj + (size_t)row * PROJ_;
#pragma unroll
    for (int k = 0; k < 16; k++) {
        int idx = tid + k * 256;
        float gt = gr[idx];
        float s = 1.f / (1.f + expf(-gt));
        float v = yr[idx] * gt * s;
        gv[k] = v;
        ss = fmaf(v, v, ss);
    }
    __shared__ float red[256];
    red[tid] = ss;
    __syncthreads();
    for (int off = 128; off > 0; off >>= 1) {
        if (tid < off) red[tid] += red[tid + off];
        __syncthreads();
    }
    float scale = rsqrtf(red[0] / (float)INTER_ + 1e-5f);
#pragma unroll
    for (int k = 0; k < 16; k++) {
        int idx = tid + k * 256;
        gf[(size_t)row * INTER_ + idx] = __float2half_rn(gv[k] * scale * nw[idx]);
    }
}

// ---------------- launch ----------------------------------------------------
extern "C" void kernel_launch(void* const* d_in, const int* in_sizes, int n_in,
                              void* d_out, int out_size)
{
    const float* hidden  = (const float*)d_in[0];
    const float* in_w    = (const float*)d_in[1];
    const float* in_b    = (const float*)d_in[2];
    const float* conv_w  = (const float*)d_in[3];
    const float* dt_bias = (const float*)d_in[4];
    const float* A_log   = (const float*)d_in[5];
    const float* Dv      = (const float*)d_in[6];
    const float* norm_w  = (const float*)d_in[7];
    const float* out_w   = (const float*)d_in[8];
    const float* out_b   = (const float*)d_in[9];
    float* out = (float*)d_out;

    float *proj, *xbc, *y, *states, *prev, *cum, *al, *Pm;
    __half *Af, *W1, *W2;
    cudaGetSymbolAddress((void**)&proj,   g_proj);
    cudaGetSymbolAddress((void**)&xbc,    g_xbc);
    cudaGetSymbolAddress((void**)&y,      g_y);
    cudaGetSymbolAddress((void**)&states, g_states);
    cudaGetSymbolAddress((void**)&prev,   g_prev);
    cudaGetSymbolAddress((void**)&cum,    g_cum);
    cudaGetSymbolAddress((void**)&al,     g_alast);
    cudaGetSymbolAddress((void**)&Pm,     g_P);
    cudaGetSymbolAddress((void**)&Af,     g_Af);
    cudaGetSymbolAddress((void**)&W1,     g_W1);
    cudaGetSymbolAddress((void**)&W2,     g_W2);

    const int SMEM_PMAT  = (128 * 68 * 2) * 4;
    const int SMEM_INTRA = (64*68*2 + 64*132 + 256*3 + 128) * 4;
    const int SMEM_OFF   = (128*68*2 + 256) * 4;
    cudaFuncSetAttribute(pmat_kernel,
                         cudaFuncAttributeMaxDynamicSharedMemorySize, SMEM_PMAT);
    cudaFuncSetAttribute(scan_intra_kernel,
                         cudaFuncAttributeMaxDynamicSharedMemorySize, SMEM_INTRA);
    cudaFuncSetAttribute(scan_off_kernel,
                         cudaFuncAttributeMaxDynamicSharedMemorySize, SMEM_OFF);
    cudaFuncSetAttribute(tc_gemm_bias,
                         cudaFuncAttributeMaxDynamicSharedMemorySize, GSMEM);

    // 0. fp16 conversions
    {
        size_t n4 = (size_t)MT * HIDDEN_ / 4;
        cvt_fp16_kernel<<<(int)((n4 + 255) / 256), 256>>>(
            (const float4*)hidden, (__half2*)Af, n4);
        size_t n4v = (size_t)PROJ_ * HIDDEN_ / 4, n4t = (size_t)NP1 * HIDDEN_ / 4;
        cvt_fp16_pad_kernel<<<(int)((n4t + 255) / 256), 256>>>(
            (const float4*)in_w, (__half2*)W1, n4v, n4t);
        n4 = (size_t)HIDDEN_ * INTER_ / 4;
        cvt_fp16_kernel<<<(int)((n4 + 255) / 256), 256>>>(
            (const float4*)out_w, (__half2*)W2, n4);
    }

    // 1. in_proj GEMM + bias (single-pass fp16 mma.sync)
    tc_gemm_bias<<<dim3(NP1 / 128, MT / 128), 256, GSMEM>>>(
        Af, W1, in_b, proj, PROJ_, HIDDEN_);

    // 2. causal depthwise conv + SiLU (rolling window)
    conv_silu_kernel<<<dim3(CONVD_ / 256, Ll / 128, Bb), 256>>>(proj, conv_w, xbc);

    // 2b. shared P = C * B^T per (b, chunk)
    pmat_kernel<<<dim3(10, NC_, Bb), 256, SMEM_PMAT>>>(xbc, Pm);

    // 3. intra-chunk scan
    scan_intra_kernel<<<dim3(NH_, NC_, Bb), 256, SMEM_INTRA>>>(
        proj, xbc, Pm, dt_bias, A_log, y, states, cum, al);

    // 4. inter-chunk recurrence
    interchunk_kernel<<<Bb * NH_, 256>>>(states, al, prev);

    // 5. inter-chunk output contribution + D skip
    scan_off_kernel<<<dim3(NH_, NC_, Bb), 256, SMEM_OFF>>>(xbc, cum, prev, Dv, y);

    // 6. gated RMSNorm -> fp16 A for GEMM2
    gated_norm_kernel<<<MT, 256>>>(proj, y, norm_w, Af);

    // 7. out_proj GEMM + bias (single-pass fp16 mma.sync)
    tc_gemm_bias<<<dim3(HIDDEN_ / 128, MT / 128), 256, GSMEM>>>(
        Af, W2, out_b, out, HIDDEN_, INTER_);
}

// round 10
// speedup vs baseline: 1.4954x; 1.1081x over previous
#include <cuda_runtime.h>
#include <cuda_bf16.h>
#include <cuda_fp16.h>
#include <math.h>
#include <cstdint>

#define Bb      2
#define Ll      2048
#define HIDDEN_ 2048
#define PROJ_   8512
#define INTER_  4096
#define CONVD_  4352
#define NH_     64
#define HD_     64
#define ST_     128
#define NC_     8
#define CS_     256
#define MT      (Bb*Ll)      // 4096
#define NP1     8576

// ---------------- static scratch ----------------
__device__ float g_proj  [(size_t)MT*PROJ_];
__device__ float g_xbc   [(size_t)MT*CONVD_];
__device__ float g_y     [(size_t)MT*INTER_];
__device__ float g_states[(size_t)Bb*NC_*NH_*HD_*ST_];
__device__ float g_prev  [(size_t)Bb*NC_*NH_*HD_*ST_];
__device__ float g_cum   [(size_t)Bb*NH_*Ll];
__device__ float g_alast [(size_t)Bb*NH_*NC_];
__device__ float g_P     [(size_t)Bb*NC_*CS_*CS_];
__device__ __half g_Af [(size_t)MT*INTER_];
__device__ __half g_W1 [(size_t)NP1*HIDDEN_];
__device__ __half g_W2 [(size_t)HIDDEN_*INTER_];

// ======================= warp-MMA helpers ====================
__device__ __forceinline__ uint32_t cvta_smem(const void* p) {
    uint32_t a;
    asm("{ .reg .u64 t; cvta.to.shared.u64 t, %1; cvt.u32.u64 %0, t; }"
        : "=r"(a) : "l"(p));
    return a;
}

__device__ __forceinline__ void ldsm4(uint32_t* r, uint32_t addr) {
    asm volatile("ldmatrix.sync.aligned.m8n8.x4.shared.b16 {%0,%1,%2,%3}, [%4];"
                 : "=r"(r[0]), "=r"(r[1]), "=r"(r[2]), "=r"(r[3]) : "r"(addr));
}

__device__ __forceinline__ void mma16816(float* c, const uint32_t* a,
                                         uint32_t b0, uint32_t b1) {
    asm volatile(
        "mma.sync.aligned.m16n8k16.row.col.f32.f16.f16.f32 "
        "{%0,%1,%2,%3}, {%4,%5,%6,%7}, {%8,%9}, {%0,%1,%2,%3};"
        : "+f"(c[0]), "+f"(c[1]), "+f"(c[2]), "+f"(c[3])
        : "r"(a[0]), "r"(a[1]), "r"(a[2]), "r"(a[3]), "r"(b0), "r"(b1));
}

// swizzled byte offset within a tile of 64-half (128B) rows
__device__ __forceinline__ uint32_t swz(int row, int col) {
    return (uint32_t)(row * 128) + (uint32_t)(((col * 2) ^ ((row & 7) << 4)));
}

#define CPASYNC16(sa, ga) \
    asm volatile("cp.async.cg.shared.global [%0], [%1], 16;" :: "r"(sa), "l"(ga) : "memory")

// GEMM tiling: BM=128, BN=128, BK=64, 256 threads, 2 CTAs/SM, 3 stages
#define ATILEB 16384u
#define STAGEB 32768u
#define NSTG   3
#define GSMEM  (1024 + NSTG*32768)

// =========================================================================
// single-pass fp16 tensor-core GEMM: C = A*W^T + bias (unchanged from R9)
// =========================================================================
__global__ __launch_bounds__(256, 2)
void tc_gemm_bias(
    const __half* __restrict__ A, const __half* __restrict__ W,
    const float* __restrict__ bias, float* __restrict__ C, int N, int K)
{
    extern __shared__ __align__(128) char smem[];
    const int tid = threadIdx.x;
    const int lid = tid & 31, wid = tid >> 5;
    uint32_t sb = cvta_smem(smem);
    uint32_t tb = (sb + 1023u) & ~1023u;

    const size_t arow = (size_t)blockIdx.y * 128;
    const size_t brow = (size_t)blockIdx.x * 128;
    const int NCH = K >> 6;

    const int seg = tid & 7, r0 = tid >> 3;
    uint32_t so[4];
#pragma unroll
    for (int k = 0; k < 4; k++) {
        uint32_t off = (uint32_t)((r0 + 32 * k) * 128 + seg * 16);
        so[k] = off ^ ((off >> 3) & 0x70);
    }
    const __half* pA = A + (arow + r0) * (size_t)K + (seg << 3);
    const __half* pW = W + (brow + r0) * (size_t)K + (seg << 3);
    const size_t off32 = (size_t)32 * K;

#define LOAD_STAGE(s)                                                     \
    do {                                                                  \
        uint32_t stb_ = tb + (uint32_t)(s) * STAGEB;                      \
        CPASYNC16(stb_ + so[0], pA);                                      \
        CPASYNC16(stb_ + so[1], pA + off32);                              \
        CPASYNC16(stb_ + so[2], pA + 2 * off32);                          \
        CPASYNC16(stb_ + so[3], pA + 3 * off32);                          \
        CPASYNC16(stb_ + ATILEB + so[0], pW);                             \
        CPASYNC16(stb_ + ATILEB + so[1], pW + off32);                     \
        CPASYNC16(stb_ + ATILEB + so[2], pW + 2 * off32);                 \
        CPASYNC16(stb_ + ATILEB + so[3], pW + 3 * off32);                 \
        asm volatile("cp.async.commit_group;" ::: "memory");              \
        pA += 64; pW += 64;                                               \
    } while (0)

    const int wm = wid & 3, wn = wid >> 2;
    const int m0 = wm * 32, n0 = wn * 64;
    const int lr  = lid & 15;
    const int lkb = (lid >> 4) * 16;

    float acc[2][8][4];
#pragma unroll
    for (int mi = 0; mi < 2; mi++)
#pragma unroll
        for (int nj = 0; nj < 8; nj++)
#pragma unroll
            for (int q = 0; q < 4; q++) acc[mi][nj][q] = 0.f;

    uint32_t aoff[2], boff[4];
#pragma unroll
    for (int mi = 0; mi < 2; mi++) {
        int row = m0 + mi * 16 + lr;
        aoff[mi] = (uint32_t)(row * 128) + (uint32_t)(((row & 7) * 16) ^ lkb);
    }
#pragma unroll
    for (int ni = 0; ni < 4; ni++) {
        int row = n0 + ni * 16 + lr;
        boff[ni] = (uint32_t)(row * 128) + (uint32_t)(((row & 7) * 16) ^ lkb);
    }

    LOAD_STAGE(0);
    LOAD_STAGE(1);

    for (int c = 0; c < NCH; c++) {
        if (c + 1 < NCH) asm volatile("cp.async.wait_group 1;" ::: "memory");
        else             asm volatile("cp.async.wait_group 0;" ::: "memory");
        __syncthreads();
        if (c + 2 < NCH) LOAD_STAGE((c + 2) % NSTG);

        uint32_t stb = tb + (uint32_t)(c % NSTG) * STAGEB;
#pragma unroll
        for (int kk = 0; kk < 4; kk++) {
            uint32_t kx = (uint32_t)(kk * 32);
            uint32_t a_f[2][4];
#pragma unroll
            for (int mi = 0; mi < 2; mi++)
                ldsm4(a_f[mi], stb + (aoff[mi] ^ kx));
            uint32_t w_f[4][4];
#pragma unroll
            for (int ni = 0; ni < 4; ni++)
                ldsm4(w_f[ni], stb + ATILEB + (boff[ni] ^ kx));
#pragma unroll
            for (int mi = 0; mi < 2; mi++)
#pragma unroll
                for (int ni = 0; ni < 4; ni++) {
                    mma16816(acc[mi][2*ni],   a_f[mi], w_f[ni][0], w_f[ni][2]);
                    mma16816(acc[mi][2*ni+1], a_f[mi], w_f[ni][1], w_f[ni][3]);
                }
        }
    }

    const int er = lid >> 2;
    const int ec = (lid & 3) * 2;
#pragma unroll
    for (int mi = 0; mi < 2; mi++) {
        int grow0 = (int)arow + m0 + mi * 16 + er;
#pragma unroll
        for (int nj = 0; nj < 8; nj++) {
            int gcol = (int)brow + n0 + nj * 8 + ec;
            if (gcol + 1 < N) {
                float b0 = __ldg(&bias[gcol]), b1 = __ldg(&bias[gcol + 1]);
                float2 v0 = {acc[mi][nj][0] + b0, acc[mi][nj][1] + b1};
                float2 v1 = {acc[mi][nj][2] + b0, acc[mi][nj][3] + b1};
                *(float2*)&C[(size_t)grow0 * N + gcol] = v0;
                *(float2*)&C[(size_t)(grow0 + 8) * N + gcol] = v1;
            } else if (gcol < N) {
                float b0 = __ldg(&bias[gcol]);
                C[(size_t)grow0 * N + gcol] = acc[mi][nj][0] + b0;
                C[(size_t)(grow0 + 8) * N + gcol] = acc[mi][nj][2] + b0;
            }
        }
    }
#undef LOAD_STAGE
}

// ---------------- fp32 -> fp16 conversions ---------------------------------
__global__ void cvt_fp16_kernel(const float4* __restrict__ src,
                                __half2* __restrict__ dst, size_t n4)
{
    size_t i = (size_t)blockIdx.x * blockDim.x + threadIdx.x;
    if (i >= n4) return;
    float4 v = src[i];
    dst[2*i]   = __floats2half2_rn(v.x, v.y);
    dst[2*i+1] = __floats2half2_rn(v.z, v.w);
}

__global__ void cvt_fp16_pad_kernel(const float4* __restrict__ src,
                                    __half2* __restrict__ dst,
                                    size_t n4v, size_t n4t)
{
    size_t i = (size_t)blockIdx.x * blockDim.x + threadIdx.x;
    if (i >= n4t) return;
    float4 v = (i < n4v) ? src[i] : make_float4(0.f, 0.f, 0.f, 0.f);
    dst[2*i]   = __floats2half2_rn(v.x, v.y);
    dst[2*i+1] = __floats2half2_rn(v.z, v.w);
}

// ---------------- causal depthwise conv (K=4) + SiLU: rolling window -------
__global__ __launch_bounds__(256) void conv_silu_kernel(
    const float* __restrict__ proj, const float* __restrict__ cw,
    float* __restrict__ xbc)
{
    const int ch = blockIdx.x * 256 + threadIdx.x;
    const int b  = blockIdx.z;
    const int t0 = blockIdx.y * 128;
    const float* col = proj + (size_t)b * Ll * PROJ_ + INTER_ + ch;
    const float4 w = *(const float4*)&cw[ch * 4];
    float xm3 = 0.f, xm2 = 0.f, xm1 = 0.f;
    if (t0 > 0) {
        xm3 = col[(size_t)(t0 - 3) * PROJ_];
        xm2 = col[(size_t)(t0 - 2) * PROJ_];
        xm1 = col[(size_t)(t0 - 1) * PROJ_];
    }
    float* dst = xbc + ((size_t)(b * Ll + t0)) * CONVD_ + ch;
    const float* srcp = col + (size_t)t0 * PROJ_;
#pragma unroll 4
    for (int k = 0; k < 128; k++) {
        float xc = srcp[(size_t)k * PROJ_];
        float acc = w.x * xm3 + w.y * xm2 + w.z * xm1 + w.w * xc;
        float sg = 1.f / (1.f + expf(-acc));
        dst[(size_t)k * CONVD_] = acc * sg;
        xm3 = xm2; xm2 = xm1; xm1 = xc;
    }
}

// ---------------- P = C * B^T (fp32, shared across heads) ------------------
__device__ __constant__ int c_PI[10] = {0,1,1,2,2,2,3,3,3,3};
__device__ __constant__ int c_PJ[10] = {0,0,1,0,1,2,0,1,2,3};

__global__ __launch_bounds__(256, 3) void pmat_kernel(
    const float* __restrict__ xbc, float* __restrict__ P)
{
    const int p = blockIdx.x, c = blockIdx.y, b = blockIdx.z;
    const int i = c_PI[p], j = c_PJ[p];
    const int tid = threadIdx.x;
    extern __shared__ float sm[];
    float* CsT = sm;              // [128][68]
    float* BsT = CsT + 128 * 68;  // [128][68]
    const size_t rowbase = (size_t)(b * Ll + c * CS_);

    for (int idx = tid; idx < 64 * 128; idx += 256) {
        int tl = idx >> 7, n = idx & 127;
        CsT[n * 68 + tl] = xbc[(rowbase + i * 64 + tl) * CONVD_ + (INTER_ + ST_) + n];
        BsT[n * 68 + tl] = xbc[(rowbase + j * 64 + tl) * CONVD_ + INTER_ + n];
    }
    __syncthreads();

    const int tx = tid & 15, ty = tid >> 4;
    const int t0 = ty * 4, s0 = tx * 4;
    float pf[4][4];
#pragma unroll
    for (int r = 0; r < 4; r++)
#pragma unroll
        for (int q = 0; q < 4; q++) pf[r][q] = 0.f;
    for (int n = 0; n < 128; n++) {
        float4 c4 = *(const float4*)&CsT[n * 68 + t0];
        float4 b4 = *(const float4*)&BsT[n * 68 + s0];
        float cr[4] = {c4.x, c4.y, c4.z, c4.w};
        float br[4] = {b4.x, b4.y, b4.z, b4.w};
#pragma unroll
        for (int r = 0; r < 4; r++)
#pragma unroll
            for (int q = 0; q < 4; q++)
                pf[r][q] = fmaf(cr[r], br[q], pf[r][q]);
    }
    float* dst = P + ((size_t)(b * NC_ + c) * CS_) * CS_;
#pragma unroll
    for (int r = 0; r < 4; r++) {
        float4 o = {pf[r][0], pf[r][1], pf[r][2], pf[r][3]};
        *(float4*)&dst[(size_t)(i * 64 + t0 + r) * CS_ + j * 64 + s0] = o;
    }
}

// ---------------- intra-chunk scan: fp16 mma version ------------------------
// smem: PwS (8KB) | xTS (8KB) | BwS (16KB) | dsh/cum/wlast/Esh (3.3KB)
__global__ __launch_bounds__(256) void scan_intra_kernel(
    const float* __restrict__ proj, const float* __restrict__ xbc,
    const float* __restrict__ gP,
    const float* __restrict__ dt_bias, const float* __restrict__ A_log,
    float* __restrict__ ydiag, float* __restrict__ states,
    float* __restrict__ cumg, float* __restrict__ alast)
{
    const int h = blockIdx.x, c = blockIdx.y, b = blockIdx.z;
    const int tid = threadIdx.x;
    extern __shared__ __align__(128) char smem[];
    char* PwS = smem;             // rows t (64), cols s (64), swizzled fp16
    char* xTS = smem + 8192;      // rows p (64), cols s (64)
    char* BwS = smem + 16384;     // rows n (128), cols s (64)
    float* dsh   = (float*)(smem + 32768);
    float* cum   = dsh + 256;
    float* wlast = cum + 256;
    float* Esh   = wlast + 256;   // [64]
    uint32_t sb = cvta_smem(smem);

    {
        float Ah = -expf(A_log[h]);
        float v = proj[(size_t)(b * Ll + c * CS_ + tid) * PROJ_ + (INTER_ + CONVD_) + h]
                + dt_bias[h];
        float dtv = (v > 20.f) ? v : log1pf(expf(v));
        dsh[tid] = dtv;
        cum[tid] = Ah * dtv;
    }
    __syncthreads();
    for (int off = 1; off < 256; off <<= 1) {
        float add = (tid >= off) ? cum[tid - off] : 0.f;
        __syncthreads();
        cum[tid] += add;
        __syncthreads();
    }
    cumg[(size_t)(b * NH_ + h) * Ll + c * CS_ + tid] = cum[tid];
    if (tid == 255) alast[(b * NH_ + h) * NC_ + c] = cum[255];
    wlast[tid] = expf(cum[255] - cum[tid]);

    const int lid = tid & 31, wid = tid >> 5;
    const int tm = (wid & 3) * 16;       // t rows (Y) / p rows (states)
    const int pn = (wid >> 2) * 32;      // p cols (Y)
    const int nn = (wid >> 2) * 64;      // n cols (states)
    const int lr = lid & 15;
    const int lkb = (lid >> 4) * 16;

    uint32_t roff;                       // A-fragment row offset (tm+lr)
    {
        int row = tm + lr;
        roff = (uint32_t)(row * 128) + (uint32_t)(((row & 7) * 16) ^ lkb);
    }
    uint32_t boffX[2], boffB[4];
#pragma unroll
    for (int ni = 0; ni < 2; ni++) {
        int row = pn + ni * 16 + lr;
        boffX[ni] = (uint32_t)(row * 128) + (uint32_t)(((row & 7) * 16) ^ lkb);
    }
#pragma unroll
    for (int ni = 0; ni < 4; ni++) {
        int row = nn + ni * 16 + lr;
        boffB[ni] = (uint32_t)(row * 128) + (uint32_t)(((row & 7) * 16) ^ lkb);
    }

    float stacc[8][4];
#pragma unroll
    for (int nj = 0; nj < 8; nj++)
#pragma unroll
        for (int q = 0; q < 4; q++) stacc[nj][q] = 0.f;

    const size_t rowbase = (size_t)(b * Ll + c * CS_);
    const float* Pblk = gP + ((size_t)(b * NC_ + c) * CS_) * CS_;
    const int sfix = tid & 63;           // fixed s / p lane for fills
    const int rfix = tid >> 6;

    for (int i = 0; i < 4; i++) {
        if (tid < 64) Esh[tid] = expf(cum[i * 64 + tid] - cum[i * 64]);
        float yacc[4][4];
#pragma unroll
        for (int nj = 0; nj < 4; nj++)
#pragma unroll
            for (int q = 0; q < 4; q++) yacc[nj][q] = 0.f;

        for (int j = 0; j <= i; j++) {
            __syncthreads();
            // fill xTS[p][s] = x(s,p)*dt(s)
            {
                const int p = sfix;
#pragma unroll
                for (int k = 0; k < 16; k++) {
                    int s = rfix + 4 * k;
                    float v = xbc[(rowbase + j * 64 + s) * CONVD_ + h * HD_ + p]
                              * dsh[j * 64 + s];
                    *(__half*)(xTS + swz(p, s)) = __float2half_rn(v);
                }
            }
            if (j == i) {
                // BwS[n][s] = wlast(s)*B(s,n)
                const int n = tid & 127;
#pragma unroll
                for (int k = 0; k < 32; k++) {
                    int s = (tid >> 7) + 2 * k;
                    float v = xbc[(rowbase + i * 64 + s) * CONVD_ + INTER_ + n]
                              * wlast[i * 64 + s];
                    *(__half*)(BwS + swz(n, s)) = __float2half_rn(v);
                }
                // PwS diagonal with causal mask
                const int s = sfix;
#pragma unroll
                for (int k = 0; k < 16; k++) {
                    int tl = rfix + 4 * k;
                    float w = (s <= tl) ? expf(cum[i*64 + tl] - cum[i*64 + s]) : 0.f;
                    *(__half*)(PwS + swz(tl, s)) =
                        __float2half_rn(Pblk[(size_t)(i*64 + tl) * CS_ + i*64 + s] * w);
                }
            } else {
                const int s = sfix;
                float rs = expf(cum[i * 64] - cum[j * 64 + s]);   // <= 1
#pragma unroll
                for (int k = 0; k < 16; k++) {
                    int tl = rfix + 4 * k;
                    *(__half*)(PwS + swz(tl, s)) =
                        __float2half_rn(Pblk[(size_t)(i*64 + tl) * CS_ + j*64 + s]
                                        * Esh[tl] * rs);
                }
            }
            __syncthreads();
            // Y mma: A = PwS (t,s), B = xTS (p,s)
            const uint32_t pwb = sb, xtb = sb + 8192u;
#pragma unroll
            for (int ks = 0; ks < 4; ks++) {
                uint32_t kx = (uint32_t)(ks * 32);
                uint32_t a[4];
                ldsm4(a, pwb + (roff ^ kx));
#pragma unroll
                for (int ni = 0; ni < 2; ni++) {
                    uint32_t bf[4];
                    ldsm4(bf, xtb + (boffX[ni] ^ kx));
                    mma16816(yacc[2*ni],   a, bf[0], bf[2]);
                    mma16816(yacc[2*ni+1], a, bf[1], bf[3]);
                }
            }
            if (j == i) {
                // states mma: A = xTS (p,s), B = BwS (n,s)
                const uint32_t bwb = sb + 16384u;
#pragma unroll
                for (int ks = 0; ks < 4; ks++) {
                    uint32_t kx = (uint32_t)(ks * 32);
                    uint32_t a[4];
                    ldsm4(a, xtb + (roff ^ kx));
#pragma unroll
                    for (int ni = 0; ni < 4; ni++) {
                        uint32_t bf[4];
                        ldsm4(bf, bwb + (boffB[ni] ^ kx));
                        mma16816(stacc[2*ni],   a, bf[0], bf[2]);
                        mma16816(stacc[2*ni+1], a, bf[1], bf[3]);
                    }
                }
            }
        }
        // Y epilogue
        {
            const int er = lid >> 2, ec = (lid & 3) * 2;
#pragma unroll
            for (int nj = 0; nj < 4; nj++) {
                int p = pn + nj * 8 + ec;
                size_t tg = rowbase + i * 64 + tm + er;
                *(float2*)&ydiag[(tg * NH_ + h) * HD_ + p] =
                    make_float2(yacc[nj][0], yacc[nj][1]);
                *(float2*)&ydiag[((tg + 8) * NH_ + h) * HD_ + p] =
                    make_float2(yacc[nj][2], yacc[nj][3]);
            }
        }
    }
    // states epilogue
    {
        const int er = lid >> 2, ec = (lid & 3) * 2;
        size_t base = ((size_t)((b * NC_ + c) * NH_ + h)) * HD_;
#pragma unroll
        for (int nj = 0; nj < 8; nj++) {
            int p = tm + er, n = nn + nj * 8 + ec;
            *(float2*)&states[(base + p) * ST_ + n] =
                make_float2(stacc[nj][0], stacc[nj][1]);
            *(float2*)&states[(base + p + 8) * ST_ + n] =
                make_float2(stacc[nj][2], stacc[nj][3]);
        }
    }
}

// ---------------- inter-chunk recurrence -----------------------------------
__global__ void interchunk_kernel(const float* __restrict__ states,
                                  const float* __restrict__ alast,
                                  float* __restrict__ prev)
{
    int bh = blockIdx.x;
    int b = bh >> 6, h = bh & 63;
    float dec[NC_];
#pragma unroll
    for (int c = 0; c < NC_; c++)
        dec[c] = expf(alast[(b * NH_ + h) * NC_ + c]);
    for (int e = threadIdx.x; e < HD_ * ST_; e += 256) {
        float run = 0.f;
#pragma unroll
        for (int c = 0; c < NC_; c++) {
            size_t idx = ((size_t)((b * NC_ + c) * NH_ + h)) * (HD_ * ST_) + e;
            prev[idx] = run;
            run = fmaf(run, dec[c] - 1.f, run);
            run = run + states[idx];
        }
    }
}

// ---------------- Y_off via fp16 mma + D-skip, accumulate into y -----------
// smem: CsS 2x(64x64) 16KB | prevS 2x(64x64) 16KB | esh 1KB
__global__ __launch_bounds__(256) void scan_off_kernel(
    const float* __restrict__ xbc, const float* __restrict__ cumg,
    const float* __restrict__ prev, const float* __restrict__ Dv,
    float* __restrict__ y)
{
    const int h = blockIdx.x, c = blockIdx.y, b = blockIdx.z;
    const int tid = threadIdx.x;
    extern __shared__ __align__(128) char smem[];
    char* CsS   = smem;             // 2 tiles of rows t(64) x cols n(64)
    char* prevS = smem + 16384;     // 2 tiles of rows p(64) x cols n(64)
    float* esh  = (float*)(smem + 32768);
    uint32_t sb = cvta_smem(smem);

    size_t sbase = ((size_t)((b * NC_ + c) * NH_ + h)) * (HD_ * ST_);
    // fill prevS fp32->fp16 (rows p, cols n)
    for (int idx = tid; idx < 64 * 128; idx += 256) {
        int p = idx >> 7, n = idx & 127;
        *(__half*)(prevS + (n >> 6) * 8192 + swz(p, n & 63)) =
            __float2half_rn(prev[sbase + idx]);
    }
    esh[tid] = expf(cumg[(size_t)(b * NH_ + h) * Ll + c * CS_ + tid]);
    const float Dh = Dv[h];
    const size_t rowbase = (size_t)(b * Ll + c * CS_);

    const int lid = tid & 31, wid = tid >> 5;
    const int tm = (wid & 3) * 16, pn = (wid >> 2) * 32;
    const int lr = lid & 15;
    const int lkb = (lid >> 4) * 16;
    uint32_t aoffC, boffP[2];
    {
        int row = tm + lr;
        aoffC = (uint32_t)(row * 128) + (uint32_t)(((row & 7) * 16) ^ lkb);
    }
#pragma unroll
    for (int ni = 0; ni < 2; ni++) {
        int row = pn + ni * 16 + lr;
        boffP[ni] = (uint32_t)(row * 128) + (uint32_t)(((row & 7) * 16) ^ lkb);
    }

    for (int ti = 0; ti < 4; ti++) {
        __syncthreads();
        // fill CsS (rows t, cols n)
        for (int idx = tid; idx < 64 * 128; idx += 256) {
            int t = idx >> 7, n = idx & 127;
            float v = xbc[(rowbase + ti * 64 + t) * CONVD_ + (INTER_ + ST_) + n];
            *(__half*)(CsS + (n >> 6) * 8192 + swz(t, n & 63)) = __float2half_rn(v);
        }
        __syncthreads();
        float acc[4][4];
#pragma unroll
        for (int nj = 0; nj < 4; nj++)
#pragma unroll
            for (int q = 0; q < 4; q++) acc[nj][q] = 0.f;
#pragma unroll
        for (int kt = 0; kt < 2; kt++) {
            uint32_t cb = sb + (uint32_t)kt * 8192u;
            uint32_t pb = sb + 16384u + (uint32_t)kt * 8192u;
#pragma unroll
            for (int ks = 0; ks < 4; ks++) {
                uint32_t kx = (uint32_t)(ks * 32);
                uint32_t a[4];
                ldsm4(a, cb + (aoffC ^ kx));
#pragma unroll
                for (int ni = 0; ni < 2; ni++) {
                    uint32_t bf[4];
                    ldsm4(bf, pb + (boffP[ni] ^ kx));
                    mma16816(acc[2*ni],   a, bf[0], bf[2]);
                    mma16816(acc[2*ni+1], a, bf[1], bf[3]);
                }
            }
        }
        // epilogue: scale by e(t), add D*x, accumulate into y
        const int er = lid >> 2, ec = (lid & 3) * 2;
#pragma unroll
        for (int nj = 0; nj < 4; nj++) {
            int p = pn + nj * 8 + ec;
            int t0g = ti * 64 + tm + er;
            size_t tg = rowbase + t0g;
            float e0 = esh[t0g], e1 = esh[t0g + 8];
            float* yp0 = y + (tg * NH_ + h) * HD_ + p;
            float* yp1 = y + ((tg + 8) * NH_ + h) * HD_ + p;
            float2 yv0 = *(float2*)yp0, yv1 = *(float2*)yp1;
            float2 xv0 = *(const float2*)&xbc[tg * CONVD_ + h * HD_ + p];
            float2 xv1 = *(const float2*)&xbc[(tg + 8) * CONVD_ + h * HD_ + p];
            yv0.x += acc[nj][0] * e0 + Dh * xv0.x;
            yv0.y += acc[nj][1] * e0 + Dh * xv0.y;
            yv1.x += acc[nj][2] * e1 + Dh * xv1.x;
            yv1.y += acc[nj][3] * e1 + Dh * xv1.y;
            *(float2*)yp0 = yv0;
            *(float2*)yp1 = yv1;
        }
    }
}

// ---------------- gated RMSNorm -> fp16 A for GEMM2 ------------------------
__global__ __launch_bounds__(256) void gated_norm_kernel(
    const float* __restrict__ proj, const float* __restrict__ y,
    const float* __restrict__ nw, __half* __restrict__ gf)
{
    int row = blockIdx.x;
    int tid = threadIdx.x;
    float gv[16];
    float ss = 0.f;
    const float* yr = y + (size_t)row * INTER_;
    const float* gr = proj + (size_t)row * PROJ_;
#pragma unroll
    for (int k = 0; k < 16; k++) {
        int idx = tid + k * 256;
        float gt = gr[idx];
        float s = 1.f / (1.f + expf(-gt));
        float v = yr[idx] * gt * s;
        gv[k] = v;
        ss = fmaf(v, v, ss);
    }
    __shared__ float red[256];
    red[tid] = ss;
    __syncthreads();
    for (int off = 128; off > 0; off >>= 1) {
        if (tid < off) red[tid] += red[tid + off];
        __syncthreads();
    }
    float scale = rsqrtf(red[0] / (float)INTER_ + 1e-5f);
#pragma unroll
    for (int k = 0; k < 16; k++) {
        int idx = tid + k * 256;
        gf[(size_t)row * INTER_ + idx] = __float2half_rn(gv[k] * scale * nw[idx]);
    }
}

// ---------------- launch ----------------------------------------------------
extern "C" void kernel_launch(void* const* d_in, const int* in_sizes, int n_in,
                              void* d_out, int out_size)
{
    const float* hidden  = (const float*)d_in[0];
    const float* in_w    = (const float*)d_in[1];
    const float* in_b    = (const float*)d_in[2];
    const float* conv_w  = (const float*)d_in[3];
    const float* dt_bias = (const float*)d_in[4];
    const float* A_log   = (const float*)d_in[5];
    const float* Dv      = (const float*)d_in[6];
    const float* norm_w  = (const float*)d_in[7];
    const float* out_w   = (const float*)d_in[8];
    const float* out_b   = (const float*)d_in[9];
    float* out = (float*)d_out;

    float *proj, *xbc, *y, *states, *prev, *cum, *al, *Pm;
    __half *Af, *W1, *W2;
    cudaGetSymbolAddress((void**)&proj,   g_proj);
    cudaGetSymbolAddress((void**)&xbc,    g_xbc);
    cudaGetSymbolAddress((void**)&y,      g_y);
    cudaGetSymbolAddress((void**)&states, g_states);
    cudaGetSymbolAddress((void**)&prev,   g_prev);
    cudaGetSymbolAddress((void**)&cum,    g_cum);
    cudaGetSymbolAddress((void**)&al,     g_alast);
    cudaGetSymbolAddress((void**)&Pm,     g_P);
    cudaGetSymbolAddress((void**)&Af,     g_Af);
    cudaGetSymbolAddress((void**)&W1,     g_W1);
    cudaGetSymbolAddress((void**)&W2,     g_W2);

    const int SMEM_PMAT  = (128 * 68 * 2) * 4;     // 69632
    const int SMEM_INTRA = 32768 + (256 * 3 + 64) * 4;   // 36096
    const int SMEM_OFF   = 32768 + 256 * 4;              // 33792
    cudaFuncSetAttribute(pmat_kernel,
                         cudaFuncAttributeMaxDynamicSharedMemorySize, SMEM_PMAT);
    cudaFuncSetAttribute(scan_intra_kernel,
                         cudaFuncAttributeMaxDynamicSharedMemorySize, SMEM_INTRA);
    cudaFuncSetAttribute(scan_off_kernel,
                         cudaFuncAttributeMaxDynamicSharedMemorySize, SMEM_OFF);
    cudaFuncSetAttribute(tc_gemm_bias,
                         cudaFuncAttributeMaxDynamicSharedMemorySize, GSMEM);

    // 0. fp16 conversions
    {
        size_t n4 = (size_t)MT * HIDDEN_ / 4;
        cvt_fp16_kernel<<<(int)((n4 + 255) / 256), 256>>>(
            (const float4*)hidden, (__half2*)Af, n4);
        size_t n4v = (size_t)PROJ_ * HIDDEN_ / 4, n4t = (size_t)NP1 * HIDDEN_ / 4;
        cvt_fp16_pad_kernel<<<(int)((n4t + 255) / 256), 256>>>(
            (const float4*)in_w, (__half2*)W1, n4v, n4t);
        n4 = (size_t)HIDDEN_ * INTER_ / 4;
        cvt_fp16_kernel<<<(int)((n4 + 255) / 256), 256>>>(
            (const float4*)out_w, (__half2*)W2, n4);
    }

    // 1. in_proj GEMM + bias
    tc_gemm_bias<<<dim3(NP1 / 128, MT / 128), 256, GSMEM>>>(
        Af, W1, in_b, proj, PROJ_, HIDDEN_);

    // 2. causal depthwise conv + SiLU
    conv_silu_kernel<<<dim3(CONVD_ / 256, Ll / 128, Bb), 256>>>(proj, conv_w, xbc);

    // 2b. shared P = C * B^T per (b, chunk)
    pmat_kernel<<<dim3(10, NC_, Bb), 256, SMEM_PMAT>>>(xbc, Pm);

    // 3. intra-chunk scan (fp16 mma)
    scan_intra_kernel<<<dim3(NH_, NC_, Bb), 256, SMEM_INTRA>>>(
        proj, xbc, Pm, dt_bias, A_log, y, states, cum, al);

    // 4. inter-chunk recurrence
    interchunk_kernel<<<Bb * NH_, 256>>>(states, al, prev);

    // 5. inter-chunk output contribution + D skip (fp16 mma)
    scan_off_kernel<<<dim3(NH_, NC_, Bb), 256, SMEM_OFF>>>(xbc, cum, prev, Dv, y);

    // 6. gated RMSNorm -> fp16 A for GEMM2
    gated_norm_kernel<<<MT, 256>>>(proj, y, norm_w, Af);

    // 7. out_proj GEMM + bias
    tc_gemm_bias<<<dim3(HIDDEN_ / 128, MT / 128), 256, GSMEM>>>(
        Af, W2, out_b, out, HIDDEN_, INTER_);
}